// round 1
// baseline (speedup 1.0000x reference)
#include <cuda_runtime.h>

#define NN 100000
#define EE 1200000
#define HD 64
#define NLAY 3

// ---------------- scratch (no allocations allowed) ----------------
__device__ float g_P[NN * HD];
__device__ float g_Q[NN * HD];
__device__ float g_xA[NN * HD];
__device__ float g_xB[NN * HD];
__device__ float g_mask[EE];
__device__ float g_rs[NN];

// ---------------- zero x_out and rowsum for this layer ----------------
__global__ void __launch_bounds__(256) zero_layer(int useB) {
    int i4 = (blockIdx.x * 256 + threadIdx.x) * 4;
    float4 z = make_float4(0.f, 0.f, 0.f, 0.f);
    float* xo = useB ? g_xB : g_xA;
    if (i4 < NN * HD) *(float4*)(xo + i4) = z;
    if (i4 < NN)      *(float4*)(g_rs + i4) = z;
}

// ---------------- per-node fused 2-stage GEMM ----------------
// blockIdx.y == 0:  P = relu(x @ W1n + b1n) @ att1W[0:64]
// blockIdx.y == 1:  Q = relu(x @ W1s + b1s) @ att1W[64:128]
// 64 nodes per block, 256 threads: thread = (node-slot 0..15) x (4 cols)
__global__ void __launch_bounds__(256) node_gemm(
    const float* __restrict__ feat, int xsel,
    const float* __restrict__ W1n, const float* __restrict__ b1n,
    const float* __restrict__ W1s, const float* __restrict__ b1s,
    const float* __restrict__ a1W)
{
    const float* x = (xsel == 0) ? feat : (xsel == 1 ? g_xA : g_xB);
    const float* W1; const float* b1; const float* W3; float* out;
    if (blockIdx.y == 0) { W1 = W1n; b1 = b1n; W3 = a1W;        out = g_P; }
    else                 { W1 = W1s; b1 = b1s; W3 = a1W + 4096; out = g_Q; }

    __shared__ float sW1[4096];
    __shared__ float sW3[4096];
    __shared__ float sX[4096];   // x tile, later overwritten by A tile

    int t = threadIdx.x;
    for (int i = 4 * t; i < 4096; i += 1024) {
        *(float4*)(sW1 + i) = *(const float4*)(W1 + i);
        *(float4*)(sW3 + i) = *(const float4*)(W3 + i);
    }
    int n0 = blockIdx.x * 64;
    for (int i = 4 * t; i < 4096; i += 1024) {
        int node = n0 + (i >> 6);
        float4 v = make_float4(0.f, 0.f, 0.f, 0.f);
        if (node < NN) v = *(const float4*)(x + (size_t)node * HD + (i & 63));
        *(float4*)(sX + i) = v;
    }
    __syncthreads();

    int c4 = (t & 15) * 4;        // 4 consecutive output columns
    int ns = (t >> 4) * 4;        // 4 node rows: ns..ns+3

    float4 bb = *(const float4*)(b1 + c4);
    float acc[4][4];
#pragma unroll
    for (int i = 0; i < 4; i++) {
        acc[i][0] = bb.x; acc[i][1] = bb.y; acc[i][2] = bb.z; acc[i][3] = bb.w;
    }
#pragma unroll 8
    for (int k = 0; k < 64; k++) {
        float4 w = *(float4*)(sW1 + k * 64 + c4);
#pragma unroll
        for (int i = 0; i < 4; i++) {
            float xb = sX[(ns + i) * 64 + k];
            acc[i][0] += xb * w.x; acc[i][1] += xb * w.y;
            acc[i][2] += xb * w.z; acc[i][3] += xb * w.w;
        }
    }
    __syncthreads();
#pragma unroll
    for (int i = 0; i < 4; i++) {
        float4 a;
        a.x = fmaxf(acc[i][0], 0.f); a.y = fmaxf(acc[i][1], 0.f);
        a.z = fmaxf(acc[i][2], 0.f); a.w = fmaxf(acc[i][3], 0.f);
        *(float4*)(sX + (ns + i) * 64 + c4) = a;
    }
    __syncthreads();

    // stage 2: P = A @ W3 (no bias, no relu)
#pragma unroll
    for (int i = 0; i < 4; i++) {
        acc[i][0] = 0.f; acc[i][1] = 0.f; acc[i][2] = 0.f; acc[i][3] = 0.f;
    }
#pragma unroll 8
    for (int k = 0; k < 64; k++) {
        float4 w = *(float4*)(sW3 + k * 64 + c4);
#pragma unroll
        for (int i = 0; i < 4; i++) {
            float ab = sX[(ns + i) * 64 + k];
            acc[i][0] += ab * w.x; acc[i][1] += ab * w.y;
            acc[i][2] += ab * w.z; acc[i][3] += ab * w.w;
        }
    }
#pragma unroll
    for (int i = 0; i < 4; i++) {
        int node = n0 + ns + i;
        if (node < NN) {
            *(float4*)(out + (size_t)node * HD + c4) =
                make_float4(acc[i][0], acc[i][1], acc[i][2], acc[i][3]);
        }
    }
}

// ---------------- edge pass 1: attention gate + rowsum ----------------
// 16 lanes per edge
__global__ void __launch_bounds__(256) edge_att(
    const int* __restrict__ row, const int* __restrict__ col,
    const float* __restrict__ b1, const float* __restrict__ w2,
    const float* __restrict__ b2)
{
    int tid = blockIdx.x * 256 + threadIdx.x;
    int e = tid >> 4;
    int lane = tid & 15;
    if (e >= EE) return;
    int r = row[e], c = col[e];
    float4 p  = *(const float4*)(g_P + r * HD + lane * 4);
    float4 q  = *(const float4*)(g_Q + c * HD + lane * 4);
    float4 bb = *(const float4*)(b1 + lane * 4);
    float4 w  = *(const float4*)(w2 + lane * 4);
    float s = fmaxf(p.x + q.x + bb.x, 0.f) * w.x
            + fmaxf(p.y + q.y + bb.y, 0.f) * w.y
            + fmaxf(p.z + q.z + bb.z, 0.f) * w.z
            + fmaxf(p.w + q.w + bb.w, 0.f) * w.w;
    s += __shfl_down_sync(0xffffffffu, s, 8, 16);
    s += __shfl_down_sync(0xffffffffu, s, 4, 16);
    s += __shfl_down_sync(0xffffffffu, s, 2, 16);
    s += __shfl_down_sync(0xffffffffu, s, 1, 16);
    if (lane == 0) {
        float la = s + b2[0];
        float m = __fdividef(1.f, 1.f + __expf(-la));   // sigmoid
        m = m * 1.5f - 0.45f;                           // *(ZETA-GAMMA)+GAMMA
        m = fminf(fmaxf(m, 0.f), 1.f);
        g_mask[e] = m;
        atomicAdd(g_rs + r, m);
    }
}

// ---------------- d^{-1/2} ----------------
__global__ void __launch_bounds__(256) dis_k() {
    int i = blockIdx.x * 256 + threadIdx.x;
    if (i < NN) g_rs[i] = fminf(rsqrtf(g_rs[i] + 1e-6f), 10.f);
}

// ---------------- edge pass 2: gated SpMM via RED atomics ----------------
__global__ void __launch_bounds__(256) edge_spmm(
    const int* __restrict__ row, const int* __restrict__ col,
    const float* __restrict__ feat, int xsel, int useB)
{
    const float* x = (xsel == 0) ? feat : (xsel == 1 ? g_xA : g_xB);
    float* xo = useB ? g_xB : g_xA;
    int tid = blockIdx.x * 256 + threadIdx.x;
    int e = tid >> 4;
    int lane = tid & 15;
    if (e >= EE) return;
    int r = row[e], c = col[e];
    float v = 0.f;
    if (lane == 0) v = g_mask[e] * g_rs[r] * g_rs[c];
    v = __shfl_sync(0xffffffffu, v, 0, 16);
    float4 xc = *(const float4*)(x + c * HD + lane * 4);
    float* dst = xo + r * HD + lane * 4;
    atomicAdd(dst + 0, v * xc.x);
    atomicAdd(dst + 1, v * xc.y);
    atomicAdd(dst + 2, v * xc.z);
    atomicAdd(dst + 3, v * xc.w);
}

// ---------------- out accumulation ----------------
__global__ void __launch_bounds__(256) accum(float* __restrict__ out,
                                             const float* __restrict__ feat,
                                             int useB, int first)
{
    int i4 = (blockIdx.x * 256 + threadIdx.x) * 4;
    if (i4 >= NN * HD) return;
    const float* xn = useB ? g_xB : g_xA;
    float4 a = first ? *(const float4*)(feat + i4) : *(const float4*)(out + i4);
    float4 b = *(const float4*)(xn + i4);
    a.x += b.x; a.y += b.y; a.z += b.z; a.w += b.w;
    *(float4*)(out + i4) = a;
}

// ---------------- launch ----------------
extern "C" void kernel_launch(void* const* d_in, const int* in_sizes, int n_in,
                              void* d_out, int out_size)
{
    const float* feat = (const float*)d_in[0];
    const float* nbW  = (const float*)d_in[1];
    const float* nbb  = (const float*)d_in[2];
    const float* sW   = (const float*)d_in[3];
    const float* sb   = (const float*)d_in[4];
    const float* a1W  = (const float*)d_in[5];
    const float* a1b  = (const float*)d_in[6];
    const float* a2W  = (const float*)d_in[7];
    const float* a2b  = (const float*)d_in[8];
    const int*   row  = (const int*)d_in[9];
    const int*   col  = (const int*)d_in[10];
    float* out = (float*)d_out;

    const int zgrid = (NN * HD / 4 + 255) / 256;   // 6250
    const int ggrid = (NN + 63) / 64;              // 1563
    const int egrid = EE / 16;                     // 75000 (16 edges/block)
    const int ngrid = (NN + 255) / 256;

    for (int l = 0; l < NLAY; l++) {
        int xsel = (l == 0) ? 0 : ((l == 1) ? 1 : 2);
        int useB = l & 1;
        zero_layer<<<zgrid, 256>>>(useB);
        node_gemm<<<dim3(ggrid, 2), 256>>>(feat, xsel,
                                           nbW + l * 4096, nbb + l * 64,
                                           sW  + l * 4096, sb  + l * 64,
                                           a1W + l * 8192);
        edge_att<<<egrid, 256>>>(row, col, a1b + l * 64, a2W + l * 64, a2b + l);
        dis_k<<<ngrid, 256>>>();
        edge_spmm<<<egrid, 256>>>(row, col, feat, xsel, useB);
        accum<<<zgrid, 256>>>(out, feat, useB, l == 0);
    }
}

// round 2
// speedup vs baseline: 1.2247x; 1.2247x over previous
#include <cuda_runtime.h>

#define NN 100000
#define EE 1200000
#define HD 64
#define NLAY 3

// ---------------- scratch (no allocations allowed) ----------------
__device__ float g_P[NN * HD];
__device__ float g_Q[NN * HD];
__device__ float g_xA[NN * HD];
__device__ float g_xB[NN * HD];
__device__ float g_mask[EE];
__device__ float g_rs[NN];

// ---------------- initial zero: g_xA and g_rs ----------------
__global__ void __launch_bounds__(256) zero_init() {
    int i4 = (blockIdx.x * 256 + threadIdx.x) * 4;
    float4 z = make_float4(0.f, 0.f, 0.f, 0.f);
    if (i4 < NN * HD) *(float4*)(g_xA + i4) = z;
    if (i4 < NN)      *(float4*)(g_rs + i4) = z;
}

// ---------------- per-node fused 2-stage GEMM ----------------
// blockIdx.y == 0:  P = relu(x @ W1n + b1n) @ att1W[0:64]
// blockIdx.y == 1:  Q = relu(x @ W1s + b1s) @ att1W[64:128]
// 64 nodes per block, 256 threads: thread = (node-slot 0..15) x (4 cols)
__global__ void __launch_bounds__(256) node_gemm(
    const float* __restrict__ feat, int xsel,
    const float* __restrict__ W1n, const float* __restrict__ b1n,
    const float* __restrict__ W1s, const float* __restrict__ b1s,
    const float* __restrict__ a1W)
{
    const float* x = (xsel == 0) ? feat : (xsel == 1 ? g_xA : g_xB);
    const float* W1; const float* b1; const float* W3; float* out;
    if (blockIdx.y == 0) { W1 = W1n; b1 = b1n; W3 = a1W;        out = g_P; }
    else                 { W1 = W1s; b1 = b1s; W3 = a1W + 4096; out = g_Q; }

    __shared__ float sW1[4096];
    __shared__ float sW3[4096];
    __shared__ float sX[4096];   // x tile, later overwritten by A tile

    int t = threadIdx.x;
    for (int i = 4 * t; i < 4096; i += 1024) {
        *(float4*)(sW1 + i) = *(const float4*)(W1 + i);
        *(float4*)(sW3 + i) = *(const float4*)(W3 + i);
    }
    int n0 = blockIdx.x * 64;
    for (int i = 4 * t; i < 4096; i += 1024) {
        int node = n0 + (i >> 6);
        float4 v = make_float4(0.f, 0.f, 0.f, 0.f);
        if (node < NN) v = *(const float4*)(x + (size_t)node * HD + (i & 63));
        *(float4*)(sX + i) = v;
    }
    __syncthreads();

    int c4 = (t & 15) * 4;        // 4 consecutive output columns
    int ns = (t >> 4) * 4;        // 4 node rows: ns..ns+3

    float4 bb = *(const float4*)(b1 + c4);
    float acc[4][4];
#pragma unroll
    for (int i = 0; i < 4; i++) {
        acc[i][0] = bb.x; acc[i][1] = bb.y; acc[i][2] = bb.z; acc[i][3] = bb.w;
    }
#pragma unroll 8
    for (int k = 0; k < 64; k++) {
        float4 w = *(float4*)(sW1 + k * 64 + c4);
#pragma unroll
        for (int i = 0; i < 4; i++) {
            float xb = sX[(ns + i) * 64 + k];
            acc[i][0] += xb * w.x; acc[i][1] += xb * w.y;
            acc[i][2] += xb * w.z; acc[i][3] += xb * w.w;
        }
    }
    __syncthreads();
#pragma unroll
    for (int i = 0; i < 4; i++) {
        float4 a;
        a.x = fmaxf(acc[i][0], 0.f); a.y = fmaxf(acc[i][1], 0.f);
        a.z = fmaxf(acc[i][2], 0.f); a.w = fmaxf(acc[i][3], 0.f);
        *(float4*)(sX + (ns + i) * 64 + c4) = a;
    }
    __syncthreads();

    // stage 2: P = A @ W3 (no bias, no relu)
#pragma unroll
    for (int i = 0; i < 4; i++) {
        acc[i][0] = 0.f; acc[i][1] = 0.f; acc[i][2] = 0.f; acc[i][3] = 0.f;
    }
#pragma unroll 8
    for (int k = 0; k < 64; k++) {
        float4 w = *(float4*)(sW3 + k * 64 + c4);
#pragma unroll
        for (int i = 0; i < 4; i++) {
            float ab = sX[(ns + i) * 64 + k];
            acc[i][0] += ab * w.x; acc[i][1] += ab * w.y;
            acc[i][2] += ab * w.z; acc[i][3] += ab * w.w;
        }
    }
#pragma unroll
    for (int i = 0; i < 4; i++) {
        int node = n0 + ns + i;
        if (node < NN) {
            *(float4*)(out + (size_t)node * HD + c4) =
                make_float4(acc[i][0], acc[i][1], acc[i][2], acc[i][3]);
        }
    }
}

// ---------------- edge pass 1: attention gate + rowsum ----------------
// 16 lanes per edge
__global__ void __launch_bounds__(256) edge_att(
    const int* __restrict__ row, const int* __restrict__ col,
    const float* __restrict__ b1, const float* __restrict__ w2,
    const float* __restrict__ b2)
{
    int tid = blockIdx.x * 256 + threadIdx.x;
    int e = tid >> 4;
    int lane = tid & 15;
    if (e >= EE) return;
    int r = row[e], c = col[e];
    float4 p  = *(const float4*)(g_P + r * HD + lane * 4);
    float4 q  = *(const float4*)(g_Q + c * HD + lane * 4);
    float4 bb = *(const float4*)(b1 + lane * 4);
    float4 w  = *(const float4*)(w2 + lane * 4);
    float s = fmaxf(p.x + q.x + bb.x, 0.f) * w.x
            + fmaxf(p.y + q.y + bb.y, 0.f) * w.y
            + fmaxf(p.z + q.z + bb.z, 0.f) * w.z
            + fmaxf(p.w + q.w + bb.w, 0.f) * w.w;
    s += __shfl_down_sync(0xffffffffu, s, 8, 16);
    s += __shfl_down_sync(0xffffffffu, s, 4, 16);
    s += __shfl_down_sync(0xffffffffu, s, 2, 16);
    s += __shfl_down_sync(0xffffffffu, s, 1, 16);
    if (lane == 0) {
        float la = s + b2[0];
        float m = __fdividef(1.f, 1.f + __expf(-la));   // sigmoid
        m = m * 1.5f - 0.45f;                           // *(ZETA-GAMMA)+GAMMA
        m = fminf(fmaxf(m, 0.f), 1.f);
        g_mask[e] = m;
        atomicAdd(g_rs + r, m);
    }
}

// ---------------- edge pass 2: gated SpMM via vector RED atomics ----------------
// d^{-1/2} computed inline from raw rowsum (saves a kernel + a pass)
__global__ void __launch_bounds__(256) edge_spmm(
    const int* __restrict__ row, const int* __restrict__ col,
    const float* __restrict__ feat, int xsel, int useB)
{
    const float* x = (xsel == 0) ? feat : (xsel == 1 ? g_xA : g_xB);
    float* xo = useB ? g_xB : g_xA;
    int tid = blockIdx.x * 256 + threadIdx.x;
    int e = tid >> 4;
    int lane = tid & 15;
    if (e >= EE) return;
    int r = row[e], c = col[e];
    float v = 0.f;
    if (lane == 0) {
        float dr = fminf(rsqrtf(g_rs[r] + 1e-6f), 10.f);
        float dc = fminf(rsqrtf(g_rs[c] + 1e-6f), 10.f);
        v = g_mask[e] * dr * dc;
    }
    v = __shfl_sync(0xffffffffu, v, (tid & 31) & ~15, 32);
    float4 xc = *(const float4*)(x + c * HD + lane * 4);
    float* dst = xo + (size_t)r * HD + lane * 4;
    asm volatile("red.global.add.v4.f32 [%0], {%1, %2, %3, %4};"
                 :: "l"(dst), "f"(v * xc.x), "f"(v * xc.y),
                    "f"(v * xc.z), "f"(v * xc.w)
                 : "memory");
}

// ---------------- out accumulation + zero next layer's buffers ----------------
__global__ void __launch_bounds__(256) accum(float* __restrict__ out,
                                             const float* __restrict__ feat,
                                             int useB, int first, int zeroNext)
{
    int i4 = (blockIdx.x * 256 + threadIdx.x) * 4;
    if (i4 >= NN * HD) return;
    const float* xn = useB ? g_xB : g_xA;
    float* xz = useB ? g_xA : g_xB;       // buffer the NEXT layer accumulates into
    float4 a = first ? *(const float4*)(feat + i4) : *(const float4*)(out + i4);
    float4 b = *(const float4*)(xn + i4);
    a.x += b.x; a.y += b.y; a.z += b.z; a.w += b.w;
    *(float4*)(out + i4) = a;
    if (zeroNext) {
        float4 z = make_float4(0.f, 0.f, 0.f, 0.f);
        *(float4*)(xz + i4) = z;
        if (i4 < NN) *(float4*)(g_rs + i4) = z;
    }
}

// ---------------- launch ----------------
extern "C" void kernel_launch(void* const* d_in, const int* in_sizes, int n_in,
                              void* d_out, int out_size)
{
    const float* feat = (const float*)d_in[0];
    const float* nbW  = (const float*)d_in[1];
    const float* nbb  = (const float*)d_in[2];
    const float* sW   = (const float*)d_in[3];
    const float* sb   = (const float*)d_in[4];
    const float* a1W  = (const float*)d_in[5];
    const float* a1b  = (const float*)d_in[6];
    const float* a2W  = (const float*)d_in[7];
    const float* a2b  = (const float*)d_in[8];
    const int*   row  = (const int*)d_in[9];
    const int*   col  = (const int*)d_in[10];
    float* out = (float*)d_out;

    const int zgrid = (NN * HD / 4 + 255) / 256;   // 6250
    const int ggrid = (NN + 63) / 64;              // 1563
    const int egrid = EE / 16;                     // 75000 (16 edges/block)

    zero_init<<<zgrid, 256>>>();
    for (int l = 0; l < NLAY; l++) {
        int xsel = (l == 0) ? 0 : ((l == 1) ? 1 : 2);
        int useB = l & 1;                 // layer 0 -> A, layer 1 -> B, layer 2 -> A
        node_gemm<<<dim3(ggrid, 2), 256>>>(feat, xsel,
                                           nbW + l * 4096, nbb + l * 64,
                                           sW  + l * 4096, sb  + l * 64,
                                           a1W + l * 8192);
        edge_att<<<egrid, 256>>>(row, col, a1b + l * 64, a2W + l * 64, a2b + l);
        edge_spmm<<<egrid, 256>>>(row, col, feat, xsel, useB);
        accum<<<zgrid, 256>>>(out, feat, useB, l == 0, l < NLAY - 1);
    }
}

// round 3
// speedup vs baseline: 1.2562x; 1.0257x over previous
#include <cuda_runtime.h>

#define NN 100000
#define EE 1200000
#define HD 64
#define NLAY 3
#define SCANB 512
#define NSCANBLK ((NN + SCANB - 1) / SCANB)   // 196

// ---------------- scratch (no allocations allowed) ----------------
__device__ float g_P[NN * HD];
__device__ float g_Q[NN * HD];
__device__ float g_xA[NN * HD];
__device__ float g_xB[NN * HD];
__device__ float g_mask[EE];
__device__ float g_rs[NN];
// CSR build
__device__ int g_cnt[NN];
__device__ int g_off[NN + 1];
__device__ int g_cur[NN];
__device__ int g_ecol[EE];
__device__ int g_bsum[256];
__device__ int g_bsum2[256];

// ================= CSR build (once per call) =================
__global__ void __launch_bounds__(256) zero_cnt() {
    int i = blockIdx.x * 256 + threadIdx.x;
    if (i < NN) g_cnt[i] = 0;
}

__global__ void __launch_bounds__(256) hist_k(const int* __restrict__ row) {
    int e = blockIdx.x * 256 + threadIdx.x;
    if (e < EE) atomicAdd(&g_cnt[row[e]], 1);
}

__global__ void __launch_bounds__(SCANB) scan1() {
    __shared__ int s[SCANB];
    int t = threadIdx.x;
    int i = blockIdx.x * SCANB + t;
    int v = (i < NN) ? g_cnt[i] : 0;
    s[t] = v;
    for (int o = 1; o < SCANB; o <<= 1) {
        __syncthreads();
        int x = (t >= o) ? s[t - o] : 0;
        __syncthreads();
        s[t] += x;
    }
    __syncthreads();
    if (i < NN) g_off[i] = s[t] - v;            // exclusive within block
    if (t == SCANB - 1) g_bsum[blockIdx.x] = s[t];
}

__global__ void __launch_bounds__(256) scan2() {
    __shared__ int s[256];
    int t = threadIdx.x;
    int v = (t < NSCANBLK) ? g_bsum[t] : 0;
    s[t] = v;
    for (int o = 1; o < 256; o <<= 1) {
        __syncthreads();
        int x = (t >= o) ? s[t - o] : 0;
        __syncthreads();
        s[t] += x;
    }
    __syncthreads();
    if (t < NSCANBLK) g_bsum2[t] = s[t] - v;    // exclusive block offsets
}

__global__ void __launch_bounds__(256) scan3() {
    int i = blockIdx.x * 256 + threadIdx.x;
    if (i < NN) {
        int o = g_off[i] + g_bsum2[i / SCANB];
        g_off[i] = o;
        g_cur[i] = o;
    }
    if (i == 0) g_off[NN] = EE;
}

__global__ void __launch_bounds__(256) scatter_k(const int* __restrict__ row,
                                                 const int* __restrict__ col) {
    int e = blockIdx.x * 256 + threadIdx.x;
    if (e < EE) {
        int pos = atomicAdd(&g_cur[row[e]], 1);
        g_ecol[pos] = col[e];
    }
}

// ---------------- per-node fused 2-stage GEMM ----------------
// blockIdx.y == 0:  P = relu(x @ W1n + b1n) @ att1W[0:64]
// blockIdx.y == 1:  Q = relu(x @ W1s + b1s) @ att1W[64:128]
__global__ void __launch_bounds__(256) node_gemm(
    const float* __restrict__ feat, int xsel,
    const float* __restrict__ W1n, const float* __restrict__ b1n,
    const float* __restrict__ W1s, const float* __restrict__ b1s,
    const float* __restrict__ a1W)
{
    const float* x = (xsel == 0) ? feat : (xsel == 1 ? g_xA : g_xB);
    const float* W1; const float* b1; const float* W3; float* out;
    if (blockIdx.y == 0) { W1 = W1n; b1 = b1n; W3 = a1W;        out = g_P; }
    else                 { W1 = W1s; b1 = b1s; W3 = a1W + 4096; out = g_Q; }

    __shared__ float sW1[4096];
    __shared__ float sW3[4096];
    __shared__ float sX[4096];

    int t = threadIdx.x;
    for (int i = 4 * t; i < 4096; i += 1024) {
        *(float4*)(sW1 + i) = *(const float4*)(W1 + i);
        *(float4*)(sW3 + i) = *(const float4*)(W3 + i);
    }
    int n0 = blockIdx.x * 64;
    for (int i = 4 * t; i < 4096; i += 1024) {
        int node = n0 + (i >> 6);
        float4 v = make_float4(0.f, 0.f, 0.f, 0.f);
        if (node < NN) v = *(const float4*)(x + (size_t)node * HD + (i & 63));
        *(float4*)(sX + i) = v;
    }
    __syncthreads();

    int c4 = (t & 15) * 4;
    int ns = (t >> 4) * 4;

    float4 bb = *(const float4*)(b1 + c4);
    float acc[4][4];
#pragma unroll
    for (int i = 0; i < 4; i++) {
        acc[i][0] = bb.x; acc[i][1] = bb.y; acc[i][2] = bb.z; acc[i][3] = bb.w;
    }
#pragma unroll 8
    for (int k = 0; k < 64; k++) {
        float4 w = *(float4*)(sW1 + k * 64 + c4);
#pragma unroll
        for (int i = 0; i < 4; i++) {
            float xb = sX[(ns + i) * 64 + k];
            acc[i][0] += xb * w.x; acc[i][1] += xb * w.y;
            acc[i][2] += xb * w.z; acc[i][3] += xb * w.w;
        }
    }
    __syncthreads();
#pragma unroll
    for (int i = 0; i < 4; i++) {
        float4 a;
        a.x = fmaxf(acc[i][0], 0.f); a.y = fmaxf(acc[i][1], 0.f);
        a.z = fmaxf(acc[i][2], 0.f); a.w = fmaxf(acc[i][3], 0.f);
        *(float4*)(sX + (ns + i) * 64 + c4) = a;
    }
    __syncthreads();

#pragma unroll
    for (int i = 0; i < 4; i++) {
        acc[i][0] = 0.f; acc[i][1] = 0.f; acc[i][2] = 0.f; acc[i][3] = 0.f;
    }
#pragma unroll 8
    for (int k = 0; k < 64; k++) {
        float4 w = *(float4*)(sW3 + k * 64 + c4);
#pragma unroll
        for (int i = 0; i < 4; i++) {
            float ab = sX[(ns + i) * 64 + k];
            acc[i][0] += ab * w.x; acc[i][1] += ab * w.y;
            acc[i][2] += ab * w.z; acc[i][3] += ab * w.w;
        }
    }
#pragma unroll
    for (int i = 0; i < 4; i++) {
        int node = n0 + ns + i;
        if (node < NN) {
            *(float4*)(out + (size_t)node * HD + c4) =
                make_float4(acc[i][0], acc[i][1], acc[i][2], acc[i][3]);
        }
    }
}

// ---------------- edge pass 1 (CSR): attention gate + rowsum, no atomics ----
// 16 lanes per row, 16 rows per 256-thread block
__global__ void __launch_bounds__(256) edge_att_csr(
    const float* __restrict__ b1, const float* __restrict__ w2,
    const float* __restrict__ b2)
{
    int t = threadIdx.x;
    int r = blockIdx.x * 16 + (t >> 4);
    int lane = t & 15;
    if (r >= NN) return;
    int start = g_off[r], end = g_off[r + 1];

    float4 p  = *(const float4*)(g_P + (size_t)r * HD + lane * 4);
    float4 bb = *(const float4*)(b1 + lane * 4);
    float4 w  = *(const float4*)(w2 + lane * 4);
    p.x += bb.x; p.y += bb.y; p.z += bb.z; p.w += bb.w;
    float b2v = b2[0];

    float rs = 0.f;
    int c = (start < end) ? g_ecol[start] : 0;
    for (int j = start; j < end; j++) {
        int cn = (j + 1 < end) ? g_ecol[j + 1] : 0;
        float4 q = *(const float4*)(g_Q + (size_t)c * HD + lane * 4);
        float s = fmaxf(p.x + q.x, 0.f) * w.x
                + fmaxf(p.y + q.y, 0.f) * w.y
                + fmaxf(p.z + q.z, 0.f) * w.z
                + fmaxf(p.w + q.w, 0.f) * w.w;
        s += __shfl_xor_sync(0xffffffffu, s, 8, 16);
        s += __shfl_xor_sync(0xffffffffu, s, 4, 16);
        s += __shfl_xor_sync(0xffffffffu, s, 2, 16);
        s += __shfl_xor_sync(0xffffffffu, s, 1, 16);
        if (lane == 0) {
            float la = s + b2v;
            float m = __fdividef(1.f, 1.f + __expf(-la));
            m = m * 1.5f - 0.45f;
            m = fminf(fmaxf(m, 0.f), 1.f);
            g_mask[j] = m;
            rs += m;
        }
        c = cn;
    }
    if (lane == 0) g_rs[r] = rs;
}

// ---------------- edge pass 2 (CSR): gated SpMM + out accumulation ----------
__global__ void __launch_bounds__(256) edge_spmm_csr(
    const float* __restrict__ feat, int xsel, int useB,
    float* __restrict__ out, int first)
{
    const float* x = (xsel == 0) ? feat : (xsel == 1 ? g_xA : g_xB);
    float* xo = useB ? g_xB : g_xA;
    int t = threadIdx.x;
    int r = blockIdx.x * 16 + (t >> 4);
    int lane = t & 15;
    if (r >= NN) return;
    int start = g_off[r], end = g_off[r + 1];

    float dr = fminf(rsqrtf(g_rs[r] + 1e-6f), 10.f);
    float4 acc = make_float4(0.f, 0.f, 0.f, 0.f);

    int c = (start < end) ? g_ecol[start] : 0;
    for (int j = start; j < end; j++) {
        int cn = (j + 1 < end) ? g_ecol[j + 1] : 0;
        float v = 0.f;
        if (lane == 0) {
            float dc = fminf(rsqrtf(g_rs[c] + 1e-6f), 10.f);
            v = g_mask[j] * dr * dc;
        }
        v = __shfl_sync(0xffffffffu, v, 0, 16);
        float4 xc = *(const float4*)(x + (size_t)c * HD + lane * 4);
        acc.x += v * xc.x; acc.y += v * xc.y;
        acc.z += v * xc.z; acc.w += v * xc.w;
        c = cn;
    }

    size_t o4 = (size_t)r * HD + lane * 4;
    *(float4*)(xo + o4) = acc;
    float4 base = first ? *(const float4*)(feat + o4) : *(const float4*)(out + o4);
    base.x += acc.x; base.y += acc.y; base.z += acc.z; base.w += acc.w;
    *(float4*)(out + o4) = base;
}

// ---------------- launch ----------------
extern "C" void kernel_launch(void* const* d_in, const int* in_sizes, int n_in,
                              void* d_out, int out_size)
{
    const float* feat = (const float*)d_in[0];
    const float* nbW  = (const float*)d_in[1];
    const float* nbb  = (const float*)d_in[2];
    const float* sW   = (const float*)d_in[3];
    const float* sb   = (const float*)d_in[4];
    const float* a1W  = (const float*)d_in[5];
    const float* a1b  = (const float*)d_in[6];
    const float* a2W  = (const float*)d_in[7];
    const float* a2b  = (const float*)d_in[8];
    const int*   row  = (const int*)d_in[9];
    const int*   col  = (const int*)d_in[10];
    float* out = (float*)d_out;

    const int ggrid = (NN + 63) / 64;      // 1563
    const int rgrid = (NN + 15) / 16;      // 6250 (16 rows/block)
    const int ngrid = (NN + 255) / 256;
    const int egrid = (EE + 255) / 256;

    // CSR build (row/col shared across layers)
    zero_cnt<<<ngrid, 256>>>();
    hist_k<<<egrid, 256>>>(row);
    scan1<<<NSCANBLK, SCANB>>>();
    scan2<<<1, 256>>>();
    scan3<<<ngrid, 256>>>();
    scatter_k<<<egrid, 256>>>(row, col);

    for (int l = 0; l < NLAY; l++) {
        int xsel = (l == 0) ? 0 : ((l == 1) ? 1 : 2);
        int useB = l & 1;
        node_gemm<<<dim3(ggrid, 2), 256>>>(feat, xsel,
                                           nbW + l * 4096, nbb + l * 64,
                                           sW  + l * 4096, sb  + l * 64,
                                           a1W + l * 8192);
        edge_att_csr<<<rgrid, 256>>>(a1b + l * 64, a2W + l * 64, a2b + l);
        edge_spmm_csr<<<rgrid, 256>>>(feat, xsel, useB, out, l == 0);
    }
}

// round 4
// speedup vs baseline: 1.9599x; 1.5601x over previous
#include <cuda_runtime.h>

#define NN 100000
#define EE 1200000
#define HD 64
#define NLAY 3
#define SCANB 512
#define NSCANBLK ((NN + SCANB - 1) / SCANB)   // 196

// ---------------- scratch (no allocations allowed) ----------------
__device__ float g_P[NN * HD];
__device__ float g_Q[NN * HD];
__device__ float g_xA[NN * HD];
__device__ float g_xB[NN * HD];
__device__ float g_mask[EE];
__device__ float g_rs[NN];
// CSR build
__device__ int g_cnt[NN];          // zero at module load; re-zeroed by scan3
__device__ int g_off[NN + 1];
__device__ int g_cur[NN];
__device__ int g_ecol[EE];
__device__ int g_bsum[256];
__device__ int g_bsum2[256];

// ---------------- f32x2 helpers (Blackwell packed FMA) ----------------
__device__ __forceinline__ unsigned long long ffma2(unsigned long long a,
                                                    unsigned long long b,
                                                    unsigned long long c) {
    unsigned long long d;
    asm("fma.rn.f32x2 %0, %1, %2, %3;" : "=l"(d) : "l"(a), "l"(b), "l"(c));
    return d;
}
__device__ __forceinline__ unsigned long long pack2(float lo, float hi) {
    unsigned long long d;
    asm("mov.b64 %0, {%1, %2};" : "=l"(d) : "f"(lo), "f"(hi));
    return d;
}
__device__ __forceinline__ float2 unpack2(unsigned long long v) {
    float2 f;
    asm("mov.b64 {%0, %1}, %2;" : "=f"(f.x), "=f"(f.y) : "l"(v));
    return f;
}

// ================= CSR build (once per call) =================
__global__ void __launch_bounds__(256) hist_k(const int* __restrict__ row) {
    int e = blockIdx.x * 256 + threadIdx.x;
    if (e < EE) atomicAdd(&g_cnt[row[e]], 1);
}

__global__ void __launch_bounds__(SCANB) scan1() {
    __shared__ int s[SCANB];
    int t = threadIdx.x;
    int i = blockIdx.x * SCANB + t;
    int v = (i < NN) ? g_cnt[i] : 0;
    s[t] = v;
    for (int o = 1; o < SCANB; o <<= 1) {
        __syncthreads();
        int x = (t >= o) ? s[t - o] : 0;
        __syncthreads();
        s[t] += x;
    }
    __syncthreads();
    if (i < NN) g_off[i] = s[t] - v;            // exclusive within block
    if (t == SCANB - 1) g_bsum[blockIdx.x] = s[t];
}

__global__ void __launch_bounds__(256) scan2() {
    __shared__ int s[256];
    int t = threadIdx.x;
    int v = (t < NSCANBLK) ? g_bsum[t] : 0;
    s[t] = v;
    for (int o = 1; o < 256; o <<= 1) {
        __syncthreads();
        int x = (t >= o) ? s[t - o] : 0;
        __syncthreads();
        s[t] += x;
    }
    __syncthreads();
    if (t < NSCANBLK) g_bsum2[t] = s[t] - v;    // exclusive block offsets
}

__global__ void __launch_bounds__(256) scan3() {
    int i = blockIdx.x * 256 + threadIdx.x;
    if (i < NN) {
        int o = g_off[i] + g_bsum2[i / SCANB];
        g_off[i] = o;
        g_cur[i] = o;
        g_cnt[i] = 0;                            // reset for next replay
    }
    if (i == 0) g_off[NN] = EE;
}

__global__ void __launch_bounds__(256) scatter_k(const int* __restrict__ row,
                                                 const int* __restrict__ col) {
    int e = blockIdx.x * 256 + threadIdx.x;
    if (e < EE) {
        int pos = atomicAdd(&g_cur[row[e]], 1);
        g_ecol[pos] = col[e];
    }
}

// ---------------- per-node fused 2-stage GEMM (f32x2 FMA) ----------------
// blockIdx.y == 0:  P = relu(x @ W1n + b1n) @ att1W[0:64]
// blockIdx.y == 1:  Q = relu(x @ W1s + b1s) @ att1W[64:128]
__global__ void __launch_bounds__(256) node_gemm(
    const float* __restrict__ feat, int xsel,
    const float* __restrict__ W1n, const float* __restrict__ b1n,
    const float* __restrict__ W1s, const float* __restrict__ b1s,
    const float* __restrict__ a1W)
{
    const float* x = (xsel == 0) ? feat : (xsel == 1 ? g_xA : g_xB);
    const float* W1; const float* b1; const float* W3; float* out;
    if (blockIdx.y == 0) { W1 = W1n; b1 = b1n; W3 = a1W;        out = g_P; }
    else                 { W1 = W1s; b1 = b1s; W3 = a1W + 4096; out = g_Q; }

    __shared__ float sW1[4096];
    __shared__ float sW3[4096];
    __shared__ float sX[4096];

    int t = threadIdx.x;
    for (int i = 4 * t; i < 4096; i += 1024) {
        *(float4*)(sW1 + i) = *(const float4*)(W1 + i);
        *(float4*)(sW3 + i) = *(const float4*)(W3 + i);
    }
    int n0 = blockIdx.x * 64;
    for (int i = 4 * t; i < 4096; i += 1024) {
        int node = n0 + (i >> 6);
        float4 v = make_float4(0.f, 0.f, 0.f, 0.f);
        if (node < NN) v = *(const float4*)(x + (size_t)node * HD + (i & 63));
        *(float4*)(sX + i) = v;
    }
    __syncthreads();

    int c4 = (t & 15) * 4;        // 4 consecutive output columns
    int ns = (t >> 4) * 4;        // 4 node rows

    float4 bb = *(const float4*)(b1 + c4);
    unsigned long long a01[4], a23[4];
    {
        unsigned long long i01 = pack2(bb.x, bb.y);
        unsigned long long i23 = pack2(bb.z, bb.w);
#pragma unroll
        for (int i = 0; i < 4; i++) { a01[i] = i01; a23[i] = i23; }
    }
#pragma unroll 8
    for (int k = 0; k < 64; k++) {
        float4 w = *(float4*)(sW1 + k * 64 + c4);
        unsigned long long w01 = pack2(w.x, w.y);
        unsigned long long w23 = pack2(w.z, w.w);
#pragma unroll
        for (int i = 0; i < 4; i++) {
            float xb = sX[(ns + i) * 64 + k];
            unsigned long long xx = pack2(xb, xb);
            a01[i] = ffma2(xx, w01, a01[i]);
            a23[i] = ffma2(xx, w23, a23[i]);
        }
    }
    __syncthreads();
#pragma unroll
    for (int i = 0; i < 4; i++) {
        float2 u01 = unpack2(a01[i]);
        float2 u23 = unpack2(a23[i]);
        float4 a;
        a.x = fmaxf(u01.x, 0.f); a.y = fmaxf(u01.y, 0.f);
        a.z = fmaxf(u23.x, 0.f); a.w = fmaxf(u23.y, 0.f);
        *(float4*)(sX + (ns + i) * 64 + c4) = a;
    }
    __syncthreads();

    // stage 2: out = A @ W3 (no bias, no relu)
#pragma unroll
    for (int i = 0; i < 4; i++) { a01[i] = 0ULL; a23[i] = 0ULL; }
#pragma unroll 8
    for (int k = 0; k < 64; k++) {
        float4 w = *(float4*)(sW3 + k * 64 + c4);
        unsigned long long w01 = pack2(w.x, w.y);
        unsigned long long w23 = pack2(w.z, w.w);
#pragma unroll
        for (int i = 0; i < 4; i++) {
            float ab = sX[(ns + i) * 64 + k];
            unsigned long long xx = pack2(ab, ab);
            a01[i] = ffma2(xx, w01, a01[i]);
            a23[i] = ffma2(xx, w23, a23[i]);
        }
    }
#pragma unroll
    for (int i = 0; i < 4; i++) {
        int node = n0 + ns + i;
        if (node < NN) {
            float2 u01 = unpack2(a01[i]);
            float2 u23 = unpack2(a23[i]);
            *(float4*)(out + (size_t)node * HD + c4) =
                make_float4(u01.x, u01.y, u23.x, u23.y);
        }
    }
}

// ---------------- gate ----------------
__device__ __forceinline__ float gatef(float la) {
    float m = __fdividef(1.f, 1.f + __expf(-la));
    m = m * 1.5f - 0.45f;
    return fminf(fmaxf(m, 0.f), 1.f);
}

// ---- edge pass 1 (CSR): attention gate + rowsum, 4-way edge unroll --------
// 16 lanes per row, 16 rows per 256-thread block. NN % 16 == 0 -> no exits.
__global__ void __launch_bounds__(256) edge_att_csr(
    const float* __restrict__ b1, const float* __restrict__ w2,
    const float* __restrict__ b2)
{
    int t = threadIdx.x;
    int r = blockIdx.x * 16 + (t >> 4);
    int lane = t & 15;
    unsigned gm = 0xFFFFu << (t & 16);     // mask for this 16-lane half

    int start = g_off[r], end = g_off[r + 1];
    float4 p  = *(const float4*)(g_P + (size_t)r * HD + lane * 4);
    float4 bb = *(const float4*)(b1 + lane * 4);
    float4 w  = *(const float4*)(w2 + lane * 4);
    p.x += bb.x; p.y += bb.y; p.z += bb.z; p.w += bb.w;
    float b2v = b2[0];

    float rs = 0.f;
    int j = start;
    for (; j + 4 <= end; j += 4) {
        int c0 = g_ecol[j + 0], c1 = g_ecol[j + 1];
        int c2 = g_ecol[j + 2], c3 = g_ecol[j + 3];
        float4 q0 = *(const float4*)(g_Q + (size_t)c0 * HD + lane * 4);
        float4 q1 = *(const float4*)(g_Q + (size_t)c1 * HD + lane * 4);
        float4 q2 = *(const float4*)(g_Q + (size_t)c2 * HD + lane * 4);
        float4 q3 = *(const float4*)(g_Q + (size_t)c3 * HD + lane * 4);
        float s0 = fmaxf(p.x + q0.x, 0.f) * w.x + fmaxf(p.y + q0.y, 0.f) * w.y
                 + fmaxf(p.z + q0.z, 0.f) * w.z + fmaxf(p.w + q0.w, 0.f) * w.w;
        float s1 = fmaxf(p.x + q1.x, 0.f) * w.x + fmaxf(p.y + q1.y, 0.f) * w.y
                 + fmaxf(p.z + q1.z, 0.f) * w.z + fmaxf(p.w + q1.w, 0.f) * w.w;
        float s2 = fmaxf(p.x + q2.x, 0.f) * w.x + fmaxf(p.y + q2.y, 0.f) * w.y
                 + fmaxf(p.z + q2.z, 0.f) * w.z + fmaxf(p.w + q2.w, 0.f) * w.w;
        float s3 = fmaxf(p.x + q3.x, 0.f) * w.x + fmaxf(p.y + q3.y, 0.f) * w.y
                 + fmaxf(p.z + q3.z, 0.f) * w.z + fmaxf(p.w + q3.w, 0.f) * w.w;
#pragma unroll
        for (int o = 8; o >= 1; o >>= 1) {
            s0 += __shfl_xor_sync(gm, s0, o, 16);
            s1 += __shfl_xor_sync(gm, s1, o, 16);
            s2 += __shfl_xor_sync(gm, s2, o, 16);
            s3 += __shfl_xor_sync(gm, s3, o, 16);
        }
        if (lane == 0) {
            float m0 = gatef(s0 + b2v), m1 = gatef(s1 + b2v);
            float m2 = gatef(s2 + b2v), m3 = gatef(s3 + b2v);
            g_mask[j + 0] = m0; g_mask[j + 1] = m1;
            g_mask[j + 2] = m2; g_mask[j + 3] = m3;
            rs += (m0 + m1) + (m2 + m3);
        }
    }
    for (; j < end; j++) {
        int c = g_ecol[j];
        float4 q = *(const float4*)(g_Q + (size_t)c * HD + lane * 4);
        float s = fmaxf(p.x + q.x, 0.f) * w.x + fmaxf(p.y + q.y, 0.f) * w.y
                + fmaxf(p.z + q.z, 0.f) * w.z + fmaxf(p.w + q.w, 0.f) * w.w;
#pragma unroll
        for (int o = 8; o >= 1; o >>= 1) s += __shfl_xor_sync(gm, s, o, 16);
        if (lane == 0) {
            float m = gatef(s + b2v);
            g_mask[j] = m;
            rs += m;
        }
    }
    if (lane == 0) g_rs[r] = rs;
}

// ---------------- d^{-1/2} in place ----------------
__global__ void __launch_bounds__(256) dis_k() {
    int i = blockIdx.x * 256 + threadIdx.x;
    if (i < NN) g_rs[i] = fminf(rsqrtf(g_rs[i] + 1e-6f), 10.f);
}

// ---- edge pass 2 (CSR): gated SpMM + out accumulation, 4-way unroll -------
__global__ void __launch_bounds__(256) edge_spmm_csr(
    const float* __restrict__ feat, int xsel, int useB,
    float* __restrict__ out, int first)
{
    const float* x = (xsel == 0) ? feat : (xsel == 1 ? g_xA : g_xB);
    float* xo = useB ? g_xB : g_xA;
    int t = threadIdx.x;
    int r = blockIdx.x * 16 + (t >> 4);
    int lane = t & 15;
    int start = g_off[r], end = g_off[r + 1];

    float dr = g_rs[r];                      // already clipped d^{-1/2}
    float4 acc = make_float4(0.f, 0.f, 0.f, 0.f);

    int j = start;
    for (; j + 4 <= end; j += 4) {
        int c0 = g_ecol[j + 0], c1 = g_ecol[j + 1];
        int c2 = g_ecol[j + 2], c3 = g_ecol[j + 3];
        float m0 = g_mask[j + 0], m1 = g_mask[j + 1];
        float m2 = g_mask[j + 2], m3 = g_mask[j + 3];
        float4 x0 = *(const float4*)(x + (size_t)c0 * HD + lane * 4);
        float4 x1 = *(const float4*)(x + (size_t)c1 * HD + lane * 4);
        float4 x2 = *(const float4*)(x + (size_t)c2 * HD + lane * 4);
        float4 x3 = *(const float4*)(x + (size_t)c3 * HD + lane * 4);
        float v0 = m0 * g_rs[c0], v1 = m1 * g_rs[c1];
        float v2 = m2 * g_rs[c2], v3 = m3 * g_rs[c3];
        acc.x += v0 * x0.x; acc.y += v0 * x0.y; acc.z += v0 * x0.z; acc.w += v0 * x0.w;
        acc.x += v1 * x1.x; acc.y += v1 * x1.y; acc.z += v1 * x1.z; acc.w += v1 * x1.w;
        acc.x += v2 * x2.x; acc.y += v2 * x2.y; acc.z += v2 * x2.z; acc.w += v2 * x2.w;
        acc.x += v3 * x3.x; acc.y += v3 * x3.y; acc.z += v3 * x3.z; acc.w += v3 * x3.w;
    }
    for (; j < end; j++) {
        int c = g_ecol[j];
        float v = g_mask[j] * g_rs[c];
        float4 xc = *(const float4*)(x + (size_t)c * HD + lane * 4);
        acc.x += v * xc.x; acc.y += v * xc.y;
        acc.z += v * xc.z; acc.w += v * xc.w;
    }
    acc.x *= dr; acc.y *= dr; acc.z *= dr; acc.w *= dr;

    size_t o4 = (size_t)r * HD + lane * 4;
    *(float4*)(xo + o4) = acc;
    float4 base = first ? *(const float4*)(feat + o4) : *(const float4*)(out + o4);
    base.x += acc.x; base.y += acc.y; base.z += acc.z; base.w += acc.w;
    *(float4*)(out + o4) = base;
}

// ---------------- launch ----------------
extern "C" void kernel_launch(void* const* d_in, const int* in_sizes, int n_in,
                              void* d_out, int out_size)
{
    const float* feat = (const float*)d_in[0];
    const float* nbW  = (const float*)d_in[1];
    const float* nbb  = (const float*)d_in[2];
    const float* sW   = (const float*)d_in[3];
    const float* sb   = (const float*)d_in[4];
    const float* a1W  = (const float*)d_in[5];
    const float* a1b  = (const float*)d_in[6];
    const float* a2W  = (const float*)d_in[7];
    const float* a2b  = (const float*)d_in[8];
    const int*   row  = (const int*)d_in[9];
    const int*   col  = (const int*)d_in[10];
    float* out = (float*)d_out;

    const int ggrid = (NN + 63) / 64;      // 1563
    const int rgrid = NN / 16;             // 6250 (16 rows/block, NN%16==0)
    const int ngrid = (NN + 255) / 256;
    const int egrid = (EE + 255) / 256;

    // CSR build (row/col shared across layers); g_cnt is zero on entry
    hist_k<<<egrid, 256>>>(row);
    scan1<<<NSCANBLK, SCANB>>>();
    scan2<<<1, 256>>>();
    scan3<<<ngrid, 256>>>();
    scatter_k<<<egrid, 256>>>(row, col);

    for (int l = 0; l < NLAY; l++) {
        int xsel = (l == 0) ? 0 : ((l == 1) ? 1 : 2);
        int useB = l & 1;
        node_gemm<<<dim3(ggrid, 2), 256>>>(feat, xsel,
                                           nbW + l * 4096, nbb + l * 64,
                                           sW  + l * 4096, sb  + l * 64,
                                           a1W + l * 8192);
        edge_att_csr<<<rgrid, 256>>>(a1b + l * 64, a2W + l * 64, a2b + l);
        dis_k<<<ngrid, 256>>>();
        edge_spmm_csr<<<rgrid, 256>>>(feat, xsel, useB, out, l == 0);
    }
}

// round 5
// speedup vs baseline: 2.0415x; 1.0417x over previous
#include <cuda_runtime.h>
#include <cuda_bf16.h>

#define NN 100000
#define EE 1200000
#define HD 64
#define NLAY 3
#define SCANB 512
#define NSCANBLK ((NN + SCANB - 1) / SCANB)   // 196

// ---------------- scratch (no allocations allowed) ----------------
__device__ __nv_bfloat162 g_P[NN * HD / 2];   // bf16 attention features
__device__ __nv_bfloat162 g_Q[NN * HD / 2];
__device__ float g_xA[NN * HD];
__device__ float g_xB[NN * HD];
__device__ float g_mask[EE];
__device__ float g_rs[NN];
// CSR build
__device__ int g_cnt[NN];          // zero at module load; re-zeroed by scan3
__device__ int g_off[NN + 1];
__device__ int g_cur[NN];
__device__ int g_ecol[EE];
__device__ int g_bsum[256];
__device__ int g_bsum2[256];

// ---------------- f32x2 helpers (Blackwell packed FMA) ----------------
__device__ __forceinline__ unsigned long long ffma2(unsigned long long a,
                                                    unsigned long long b,
                                                    unsigned long long c) {
    unsigned long long d;
    asm("fma.rn.f32x2 %0, %1, %2, %3;" : "=l"(d) : "l"(a), "l"(b), "l"(c));
    return d;
}
__device__ __forceinline__ unsigned long long pack2(float lo, float hi) {
    unsigned long long d;
    asm("mov.b64 %0, {%1, %2};" : "=l"(d) : "f"(lo), "f"(hi));
    return d;
}
__device__ __forceinline__ float2 unpack2(unsigned long long v) {
    float2 f;
    asm("mov.b64 {%0, %1}, %2;" : "=f"(f.x), "=f"(f.y) : "l"(v));
    return f;
}

// ================= CSR build (once per call) =================
__global__ void __launch_bounds__(256) hist_k(const int* __restrict__ row) {
    int e = blockIdx.x * 256 + threadIdx.x;
    if (e < EE) atomicAdd(&g_cnt[row[e]], 1);
}

__global__ void __launch_bounds__(SCANB) scan1() {
    __shared__ int s[SCANB];
    int t = threadIdx.x;
    int i = blockIdx.x * SCANB + t;
    int v = (i < NN) ? g_cnt[i] : 0;
    s[t] = v;
    for (int o = 1; o < SCANB; o <<= 1) {
        __syncthreads();
        int x = (t >= o) ? s[t - o] : 0;
        __syncthreads();
        s[t] += x;
    }
    __syncthreads();
    if (i < NN) g_off[i] = s[t] - v;
    if (t == SCANB - 1) g_bsum[blockIdx.x] = s[t];
}

__global__ void __launch_bounds__(256) scan2() {
    __shared__ int s[256];
    int t = threadIdx.x;
    int v = (t < NSCANBLK) ? g_bsum[t] : 0;
    s[t] = v;
    for (int o = 1; o < 256; o <<= 1) {
        __syncthreads();
        int x = (t >= o) ? s[t - o] : 0;
        __syncthreads();
        s[t] += x;
    }
    __syncthreads();
    if (t < NSCANBLK) g_bsum2[t] = s[t] - v;
}

__global__ void __launch_bounds__(256) scan3() {
    int i = blockIdx.x * 256 + threadIdx.x;
    if (i < NN) {
        int o = g_off[i] + g_bsum2[i / SCANB];
        g_off[i] = o;
        g_cur[i] = o;
        g_cnt[i] = 0;
    }
    if (i == 0) g_off[NN] = EE;
}

__global__ void __launch_bounds__(256) scatter_k(const int* __restrict__ row,
                                                 const int* __restrict__ col) {
    int e = blockIdx.x * 256 + threadIdx.x;
    if (e < EE) {
        int pos = atomicAdd(&g_cur[row[e]], 1);
        g_ecol[pos] = col[e];
    }
}

// ---------------- per-node fused 2-stage GEMM (f32x2 FMA, bf16 out) -------
__global__ void __launch_bounds__(256) node_gemm(
    const float* __restrict__ feat, int xsel,
    const float* __restrict__ W1n, const float* __restrict__ b1n,
    const float* __restrict__ W1s, const float* __restrict__ b1s,
    const float* __restrict__ a1W)
{
    const float* x = (xsel == 0) ? feat : (xsel == 1 ? g_xA : g_xB);
    const float* W1; const float* b1; const float* W3; __nv_bfloat162* out;
    if (blockIdx.y == 0) { W1 = W1n; b1 = b1n; W3 = a1W;        out = g_P; }
    else                 { W1 = W1s; b1 = b1s; W3 = a1W + 4096; out = g_Q; }

    __shared__ float sW1[4096];
    __shared__ float sW3[4096];
    __shared__ float sX[4096];

    int t = threadIdx.x;
    for (int i = 4 * t; i < 4096; i += 1024) {
        *(float4*)(sW1 + i) = *(const float4*)(W1 + i);
        *(float4*)(sW3 + i) = *(const float4*)(W3 + i);
    }
    int n0 = blockIdx.x * 64;
    for (int i = 4 * t; i < 4096; i += 1024) {
        int node = n0 + (i >> 6);
        float4 v = make_float4(0.f, 0.f, 0.f, 0.f);
        if (node < NN) v = *(const float4*)(x + (size_t)node * HD + (i & 63));
        *(float4*)(sX + i) = v;
    }
    __syncthreads();

    int c4 = (t & 15) * 4;
    int ns = (t >> 4) * 4;

    float4 bb = *(const float4*)(b1 + c4);
    unsigned long long a01[4], a23[4];
    {
        unsigned long long i01 = pack2(bb.x, bb.y);
        unsigned long long i23 = pack2(bb.z, bb.w);
#pragma unroll
        for (int i = 0; i < 4; i++) { a01[i] = i01; a23[i] = i23; }
    }
#pragma unroll 8
    for (int k = 0; k < 64; k++) {
        float4 w = *(float4*)(sW1 + k * 64 + c4);
        unsigned long long w01 = pack2(w.x, w.y);
        unsigned long long w23 = pack2(w.z, w.w);
#pragma unroll
        for (int i = 0; i < 4; i++) {
            float xb = sX[(ns + i) * 64 + k];
            unsigned long long xx = pack2(xb, xb);
            a01[i] = ffma2(xx, w01, a01[i]);
            a23[i] = ffma2(xx, w23, a23[i]);
        }
    }
    __syncthreads();
#pragma unroll
    for (int i = 0; i < 4; i++) {
        float2 u01 = unpack2(a01[i]);
        float2 u23 = unpack2(a23[i]);
        float4 a;
        a.x = fmaxf(u01.x, 0.f); a.y = fmaxf(u01.y, 0.f);
        a.z = fmaxf(u23.x, 0.f); a.w = fmaxf(u23.y, 0.f);
        *(float4*)(sX + (ns + i) * 64 + c4) = a;
    }
    __syncthreads();

#pragma unroll
    for (int i = 0; i < 4; i++) { a01[i] = 0ULL; a23[i] = 0ULL; }
#pragma unroll 8
    for (int k = 0; k < 64; k++) {
        float4 w = *(float4*)(sW3 + k * 64 + c4);
        unsigned long long w01 = pack2(w.x, w.y);
        unsigned long long w23 = pack2(w.z, w.w);
#pragma unroll
        for (int i = 0; i < 4; i++) {
            float ab = sX[(ns + i) * 64 + k];
            unsigned long long xx = pack2(ab, ab);
            a01[i] = ffma2(xx, w01, a01[i]);
            a23[i] = ffma2(xx, w23, a23[i]);
        }
    }
#pragma unroll
    for (int i = 0; i < 4; i++) {
        int node = n0 + ns + i;
        if (node < NN) {
            float2 u01 = unpack2(a01[i]);
            float2 u23 = unpack2(a23[i]);
            __nv_bfloat162 b0 = __float22bfloat162_rn(u01);
            __nv_bfloat162 b1v = __float22bfloat162_rn(u23);
            // 32 bf162 per node row; this thread owns pair (c4/2, c4/2+1)
            *(uint2*)(out + (size_t)node * 32 + (c4 >> 1)) =
                make_uint2(*(unsigned*)&b0, *(unsigned*)&b1v);
        }
    }
}

// ---------------- gate ----------------
__device__ __forceinline__ float gatef(float la) {
    float m = __fdividef(1.f, 1.f + __expf(-la));
    m = m * 1.5f - 0.45f;
    return fminf(fmaxf(m, 0.f), 1.f);
}

__device__ __forceinline__ float dot_pq(float4 p, uint2 qv, float4 w) {
    __nv_bfloat162 qa = *(__nv_bfloat162*)&qv.x;
    __nv_bfloat162 qb = *(__nv_bfloat162*)&qv.y;
    float2 q01 = __bfloat1622float2(qa);
    float2 q23 = __bfloat1622float2(qb);
    return fmaxf(p.x + q01.x, 0.f) * w.x + fmaxf(p.y + q01.y, 0.f) * w.y
         + fmaxf(p.z + q23.x, 0.f) * w.z + fmaxf(p.w + q23.y, 0.f) * w.w;
}

// ---- edge pass 1 (CSR): attention gate + rowsum, 4-way edge unroll --------
__global__ void __launch_bounds__(256) edge_att_csr(
    const float* __restrict__ b1, const float* __restrict__ w2,
    const float* __restrict__ b2)
{
    int t = threadIdx.x;
    int r = blockIdx.x * 16 + (t >> 4);
    int lane = t & 15;
    unsigned gm = 0xFFFFu << (t & 16);

    int start = g_off[r], end = g_off[r + 1];
    uint2 pv = *(const uint2*)(g_P + (size_t)r * 32 + lane * 2);
    float2 p01 = __bfloat1622float2(*(__nv_bfloat162*)&pv.x);
    float2 p23 = __bfloat1622float2(*(__nv_bfloat162*)&pv.y);
    float4 bb = *(const float4*)(b1 + lane * 4);
    float4 w  = *(const float4*)(w2 + lane * 4);
    float4 p = make_float4(p01.x + bb.x, p01.y + bb.y, p23.x + bb.z, p23.y + bb.w);
    float b2v = b2[0];

    float rs = 0.f;
    int j = start;
    for (; j + 4 <= end; j += 4) {
        int c0 = g_ecol[j + 0], c1 = g_ecol[j + 1];
        int c2 = g_ecol[j + 2], c3 = g_ecol[j + 3];
        uint2 q0 = *(const uint2*)(g_Q + (size_t)c0 * 32 + lane * 2);
        uint2 q1 = *(const uint2*)(g_Q + (size_t)c1 * 32 + lane * 2);
        uint2 q2 = *(const uint2*)(g_Q + (size_t)c2 * 32 + lane * 2);
        uint2 q3 = *(const uint2*)(g_Q + (size_t)c3 * 32 + lane * 2);
        float s0 = dot_pq(p, q0, w);
        float s1 = dot_pq(p, q1, w);
        float s2 = dot_pq(p, q2, w);
        float s3 = dot_pq(p, q3, w);
#pragma unroll
        for (int o = 8; o >= 1; o >>= 1) {
            s0 += __shfl_xor_sync(gm, s0, o, 16);
            s1 += __shfl_xor_sync(gm, s1, o, 16);
            s2 += __shfl_xor_sync(gm, s2, o, 16);
            s3 += __shfl_xor_sync(gm, s3, o, 16);
        }
        if (lane == 0) {
            float m0 = gatef(s0 + b2v), m1 = gatef(s1 + b2v);
            float m2 = gatef(s2 + b2v), m3 = gatef(s3 + b2v);
            g_mask[j + 0] = m0; g_mask[j + 1] = m1;
            g_mask[j + 2] = m2; g_mask[j + 3] = m3;
            rs += (m0 + m1) + (m2 + m3);
        }
    }
    for (; j < end; j++) {
        int c = g_ecol[j];
        uint2 q = *(const uint2*)(g_Q + (size_t)c * 32 + lane * 2);
        float s = dot_pq(p, q, w);
#pragma unroll
        for (int o = 8; o >= 1; o >>= 1) s += __shfl_xor_sync(gm, s, o, 16);
        if (lane == 0) {
            float m = gatef(s + b2v);
            g_mask[j] = m;
            rs += m;
        }
    }
    if (lane == 0) g_rs[r] = rs;
}

// ---------------- d^{-1/2} in place ----------------
__global__ void __launch_bounds__(256) dis_k() {
    int i = blockIdx.x * 256 + threadIdx.x;
    if (i < NN) g_rs[i] = fminf(rsqrtf(g_rs[i] + 1e-6f), 10.f);
}

// ---- edge pass 2 (CSR): gated SpMM + out accumulation, 4-way unroll -------
__global__ void __launch_bounds__(256) edge_spmm_csr(
    const float* __restrict__ feat, int xsel, int useB,
    float* __restrict__ out, int first)
{
    const float* x = (xsel == 0) ? feat : (xsel == 1 ? g_xA : g_xB);
    float* xo = useB ? g_xB : g_xA;
    int t = threadIdx.x;
    int r = blockIdx.x * 16 + (t >> 4);
    int lane = t & 15;
    int start = g_off[r], end = g_off[r + 1];

    float dr = g_rs[r];
    float4 acc = make_float4(0.f, 0.f, 0.f, 0.f);

    int j = start;
    for (; j + 4 <= end; j += 4) {
        int c0 = g_ecol[j + 0], c1 = g_ecol[j + 1];
        int c2 = g_ecol[j + 2], c3 = g_ecol[j + 3];
        float m0 = g_mask[j + 0], m1 = g_mask[j + 1];
        float m2 = g_mask[j + 2], m3 = g_mask[j + 3];
        float4 x0 = *(const float4*)(x + (size_t)c0 * HD + lane * 4);
        float4 x1 = *(const float4*)(x + (size_t)c1 * HD + lane * 4);
        float4 x2 = *(const float4*)(x + (size_t)c2 * HD + lane * 4);
        float4 x3 = *(const float4*)(x + (size_t)c3 * HD + lane * 4);
        float v0 = m0 * g_rs[c0], v1 = m1 * g_rs[c1];
        float v2 = m2 * g_rs[c2], v3 = m3 * g_rs[c3];
        acc.x += v0 * x0.x; acc.y += v0 * x0.y; acc.z += v0 * x0.z; acc.w += v0 * x0.w;
        acc.x += v1 * x1.x; acc.y += v1 * x1.y; acc.z += v1 * x1.z; acc.w += v1 * x1.w;
        acc.x += v2 * x2.x; acc.y += v2 * x2.y; acc.z += v2 * x2.z; acc.w += v2 * x2.w;
        acc.x += v3 * x3.x; acc.y += v3 * x3.y; acc.z += v3 * x3.z; acc.w += v3 * x3.w;
    }
    for (; j < end; j++) {
        int c = g_ecol[j];
        float v = g_mask[j] * g_rs[c];
        float4 xc = *(const float4*)(x + (size_t)c * HD + lane * 4);
        acc.x += v * xc.x; acc.y += v * xc.y;
        acc.z += v * xc.z; acc.w += v * xc.w;
    }
    acc.x *= dr; acc.y *= dr; acc.z *= dr; acc.w *= dr;

    size_t o4 = (size_t)r * HD + lane * 4;
    *(float4*)(xo + o4) = acc;
    float4 base = first ? *(const float4*)(feat + o4) : *(const float4*)(out + o4);
    base.x += acc.x; base.y += acc.y; base.z += acc.z; base.w += acc.w;
    *(float4*)(out + o4) = base;
}

// ---------------- launch ----------------
extern "C" void kernel_launch(void* const* d_in, const int* in_sizes, int n_in,
                              void* d_out, int out_size)
{
    const float* feat = (const float*)d_in[0];
    const float* nbW  = (const float*)d_in[1];
    const float* nbb  = (const float*)d_in[2];
    const float* sW   = (const float*)d_in[3];
    const float* sb   = (const float*)d_in[4];
    const float* a1W  = (const float*)d_in[5];
    const float* a1b  = (const float*)d_in[6];
    const float* a2W  = (const float*)d_in[7];
    const float* a2b  = (const float*)d_in[8];
    const int*   row  = (const int*)d_in[9];
    const int*   col  = (const int*)d_in[10];
    float* out = (float*)d_out;

    const int ggrid = (NN + 63) / 64;      // 1563
    const int rgrid = NN / 16;             // 6250
    const int ngrid = (NN + 255) / 256;
    const int egrid = (EE + 255) / 256;

    hist_k<<<egrid, 256>>>(row);
    scan1<<<NSCANBLK, SCANB>>>();
    scan2<<<1, 256>>>();
    scan3<<<ngrid, 256>>>();
    scatter_k<<<egrid, 256>>>(row, col);

    for (int l = 0; l < NLAY; l++) {
        int xsel = (l == 0) ? 0 : ((l == 1) ? 1 : 2);
        int useB = l & 1;
        node_gemm<<<dim3(ggrid, 2), 256>>>(feat, xsel,
                                           nbW + l * 4096, nbb + l * 64,
                                           sW  + l * 4096, sb  + l * 64,
                                           a1W + l * 8192);
        edge_att_csr<<<rgrid, 256>>>(a1b + l * 64, a2W + l * 64, a2b + l);
        dis_k<<<ngrid, 256>>>();
        edge_spmm_csr<<<rgrid, 256>>>(feat, xsel, useB, out, l == 0);
    }
}